// round 7
// baseline (speedup 1.0000x reference)
#include <cuda_runtime.h>
#include <cstddef>

// 2-layer LSTM (H=20) + FC head, B=4096, T=512, D=1.
// 8 lanes/seq, 1 seq/thread, 256-thread blocks -> 1024 warps (2 per SMSP).
// m-pair-packed weights (fma.rn.f32x2), h exchanged via conflict-free shared
// (group stride 20 floats), role-split activations (p0: i,f ; p1: g,o).

using u64 = unsigned long long;

__device__ __forceinline__ u64 fma2(u64 a, u64 b, u64 c) {
    u64 d;
    asm("fma.rn.f32x2 %0, %1, %2, %3;" : "=l"(d) : "l"(a), "l"(b), "l"(c));
    return d;
}
__device__ __forceinline__ u64 pk2(float lo, float hi) {
    u64 r;
    asm("mov.b64 %0, {%1, %2};" : "=l"(r) : "f"(lo), "f"(hi));
    return r;
}
__device__ __forceinline__ void up2(float& lo, float& hi, u64 v) {
    asm("mov.b64 {%0, %1}, %2;" : "=f"(lo), "=f"(hi) : "l"(v));
}
__device__ __forceinline__ float ex2_(float x) {
    float y; asm("ex2.approx.f32 %0, %1;" : "=f"(y) : "f"(x)); return y;
}
__device__ __forceinline__ float rcp_(float x) {
    float y; asm("rcp.approx.f32 %0, %1;" : "=f"(y) : "f"(x)); return y;
}

#define L2E 1.4426950408889634f
#define W1S 22   // layer1 row stride in u64: [u 10][v 10][pad 2] = 176 B

__global__ void __launch_bounds__(256, 1) lstm2_fc_kernel(
    const float* __restrict__ x,     // [B, T]
    const float* __restrict__ Wih0,  // [80, 1]
    const float* __restrict__ Whh0,  // [80, 20]
    const float* __restrict__ bih0,  // [80]
    const float* __restrict__ bhh0,  // [80]
    const float* __restrict__ Wih1,  // [80, 20]
    const float* __restrict__ Whh1,  // [80, 20]
    const float* __restrict__ bih1,  // [80]
    const float* __restrict__ bhh1,  // [80]
    const float* __restrict__ fcW,   // [1, 20]
    const float* __restrict__ fcb,   // [1]
    float* __restrict__ out,         // [B, 1]
    int Btot, int Tlen)
{
    // w0: [rr=gl*5+jl][lane8][10 k]  (80B lane stride -> conflict-free)
    // w1: [rr][lane8][W1S]           (176B lane stride -> conflict-free)
    __shared__ __align__(16) u64 w0[10 * 8 * 10];
    __shared__ __align__(16) u64 w1[10 * 8 * W1S];
    // h exchange: per-group 20 floats, stride exactly 20 (banks 5*(4g+q)+jl distinct)
    __shared__ __align__(16) float hg0[32 * 20];
    __shared__ __align__(16) float hg1[32 * 20];

    const int tid = threadIdx.x;

    for (int idx = tid; idx < 800; idx += 256) {
        int k = idx % 10, lane8 = (idx / 10) % 8, rr = idx / 80;
        int p = lane8 >> 2, q = lane8 & 3, gl = rr / 5, jl = rr % 5;
        int r = (p * 2 + gl) * 20 + q * 5 + jl;
        w0[(rr * 8 + lane8) * 10 + k] = pk2(Whh0[r * 20 + 2 * k], Whh0[r * 20 + 2 * k + 1]);
    }
    for (int idx = tid; idx < 1600; idx += 256) {
        int k = idx % 20, lane8 = (idx / 20) % 8, rr = idx / 160;
        int p = lane8 >> 2, q = lane8 & 3, gl = rr / 5, jl = rr % 5;
        int r = (p * 2 + gl) * 20 + q * 5 + jl;
        const float* mat = (k < 10) ? Wih1 : Whh1;
        int km = (k < 10) ? k : (k - 10);
        w1[(rr * 8 + lane8) * W1S + k] = pk2(mat[r * 20 + 2 * km], mat[r * 20 + 2 * km + 1]);
    }
    __syncthreads();

    // ---- lane mapping ----
    const int g2  = tid >> 3;        // group (sequence) 0..31 within block
    const int sub = tid & 7;
    const int p   = sub >> 2;        // 0: gates i,f ; 1: gates g,o
    const int q   = sub & 3;
    const int lane8 = sub;
    const bool isP1 = (p == 1);

    int b = blockIdx.x * 32 + g2;
    const bool active = (b < Btot);
    if (b >= Btot) b = Btot - 1;
    const float* xb = x + (size_t)b * Tlen;

    // per-lane row scalars (from global; tiny, one-time)
    float b0r[2][5], b1r[2][5], wxr[2][5];
    #pragma unroll
    for (int gl = 0; gl < 2; ++gl)
        #pragma unroll
        for (int jl = 0; jl < 5; ++jl) {
            int r = (p * 2 + gl) * 20 + q * 5 + jl;
            b0r[gl][jl] = __ldg(&bih0[r]) + __ldg(&bhh0[r]);
            b1r[gl][jl] = __ldg(&bih1[r]) + __ldg(&bhh1[r]);
            wxr[gl][jl] = __ldg(&Wih0[r]);
        }

    // activation constants: lo-gate = sigmoid (p0: i) or tanh (p1: g)
    const float kk0 = isP1 ? (-2.0f * L2E) : (-L2E);
    const float kb2 = isP1 ? 2.0f : 1.0f;
    const float kb3 = isP1 ? -1.0f : 0.0f;

    u64 hh[10], hb[10];              // m-packed h0 / h1
    float c0[5], c1[5];
    #pragma unroll
    for (int i = 0; i < 10; ++i) { hh[i] = 0ull; hb[i] = 0ull; }
    #pragma unroll
    for (int i = 0; i < 5; ++i) { c0[i] = 0.f; c1[i] = 0.f; }

    const unsigned FULL = 0xffffffffu;
    float* myh0 = &hg0[g2 * 20 + q * 5];
    float* myh1 = &hg1[g2 * 20 + q * 5];
    const float* ldh0 = &hg0[g2 * 20];
    const float* ldh1 = &hg1[g2 * 20];

    float xn = __ldg(&xb[0]);

    #pragma unroll 1
    for (int t = 0; t < Tlen; ++t) {
        const float xt = xn;
        if (t + 1 < Tlen) xn = __ldg(&xb[t + 1]);

        // ================= layer 0 =================
        #pragma unroll
        for (int jl = 0; jl < 5; ++jl) {
            const u64* base0 = &w0[((0 + jl) * 8 + lane8) * 10];
            const u64* base1 = &w0[((5 + jl) * 8 + lane8) * 10];
            u64 a0 = pk2(fmaf(wxr[0][jl], xt, b0r[0][jl]), 0.f);
            u64 a1 = pk2(fmaf(wxr[1][jl], xt, b0r[1][jl]), 0.f);
            #pragma unroll
            for (int k = 0; k < 10; ++k) {
                a0 = fma2(base0[k], hh[k], a0);
                a1 = fma2(base1[k], hh[k], a1);
            }
            float l0, h0, l1, h1;
            up2(l0, h0, a0); up2(l1, h1, a1);
            float g0 = l0 + h0, g1 = l1 + h1;

            float act0 = fmaf(kb2, rcp_(1.0f + ex2_(kk0 * g0)), kb3); // sigm(i)|tanh(g)
            float act1 = rcp_(1.0f + ex2_(-L2E * g1));                 // sigm(f)|sigm(o)
            float x0 = __shfl_xor_sync(FULL, act0, 4, 8);
            float x1 = __shfl_xor_sync(FULL, act1, 4, 8);
            float gi = isP1 ? x0 : act0, gg = isP1 ? act0 : x0;
            float gf = isP1 ? x1 : act1, go = isP1 ? act1 : x1;
            float cn = fmaf(gf, c0[jl], gi * gg);
            c0[jl] = cn;
            float tc = fmaf(2.0f, rcp_(1.0f + ex2_(-2.0f * L2E * cn)), -1.0f);
            float hv = go * tc;
            if (!isP1) myh0[jl] = hv;
        }
        __syncwarp(FULL);
        #pragma unroll
        for (int k2 = 0; k2 < 5; ++k2) {
            ulonglong2 v = *reinterpret_cast<const ulonglong2*>(&ldh0[4 * k2]);
            hh[2 * k2] = v.x; hh[2 * k2 + 1] = v.y;
        }

        // ================= layer 1 =================
        #pragma unroll
        for (int jl = 0; jl < 5; ++jl) {
            const u64* base0 = &w1[((0 + jl) * 8 + lane8) * W1S];
            const u64* base1 = &w1[((5 + jl) * 8 + lane8) * W1S];
            u64 a0 = pk2(b1r[0][jl], 0.f);
            u64 a1 = pk2(b1r[1][jl], 0.f);
            #pragma unroll
            for (int k = 0; k < 10; ++k) {
                a0 = fma2(base0[k],      hh[k], a0);
                a1 = fma2(base1[k],      hh[k], a1);
                a0 = fma2(base0[10 + k], hb[k], a0);
                a1 = fma2(base1[10 + k], hb[k], a1);
            }
            float l0, h0, l1, h1;
            up2(l0, h0, a0); up2(l1, h1, a1);
            float g0 = l0 + h0, g1 = l1 + h1;

            float act0 = fmaf(kb2, rcp_(1.0f + ex2_(kk0 * g0)), kb3);
            float act1 = rcp_(1.0f + ex2_(-L2E * g1));
            float x0 = __shfl_xor_sync(FULL, act0, 4, 8);
            float x1 = __shfl_xor_sync(FULL, act1, 4, 8);
            float gi = isP1 ? x0 : act0, gg = isP1 ? act0 : x0;
            float gf = isP1 ? x1 : act1, go = isP1 ? act1 : x1;
            float cn = fmaf(gf, c1[jl], gi * gg);
            c1[jl] = cn;
            float tc = fmaf(2.0f, rcp_(1.0f + ex2_(-2.0f * L2E * cn)), -1.0f);
            float hv = go * tc;
            if (!isP1) myh1[jl] = hv;
        }
        __syncwarp(FULL);
        #pragma unroll
        for (int k2 = 0; k2 < 5; ++k2) {
            ulonglong2 v = *reinterpret_cast<const ulonglong2*>(&ldh1[4 * k2]);
            hb[2 * k2] = v.x; hb[2 * k2 + 1] = v.y;
        }
    }

    // ---- FC head: hb holds final h1 (m-packed, all lanes) ----
    if (sub == 0) {
        u64 accF = 0ull;
        #pragma unroll
        for (int k = 0; k < 10; ++k) {
            u64 f2 = pk2(__ldg(&fcW[2 * k]), __ldg(&fcW[2 * k + 1]));
            accF = fma2(f2, hb[k], accF);
        }
        float fl, fh;
        up2(fl, fh, accF);
        if (active) out[b] = fl + fh + __ldg(&fcb[0]);
    }
}

extern "C" void kernel_launch(void* const* d_in, const int* in_sizes, int n_in,
                              void* d_out, int out_size)
{
    const float* x    = (const float*)d_in[0];
    const float* Wih0 = (const float*)d_in[1];
    const float* Whh0 = (const float*)d_in[2];
    const float* bih0 = (const float*)d_in[3];
    const float* bhh0 = (const float*)d_in[4];
    const float* Wih1 = (const float*)d_in[5];
    const float* Whh1 = (const float*)d_in[6];
    const float* bih1 = (const float*)d_in[7];
    const float* bhh1 = (const float*)d_in[8];
    const float* fcW  = (const float*)d_in[9];
    const float* fcb  = (const float*)d_in[10];

    const int B = out_size;              // out is [B, 1] fp32
    const int T = in_sizes[0] / B;       // x is [B, T, 1]
    const int blocks = (B + 31) / 32;    // 32 seqs per 256-thread block

    lstm2_fc_kernel<<<blocks, 256>>>(x, Wih0, Whh0, bih0, bhh0,
                                     Wih1, Whh1, bih1, bhh1,
                                     fcW, fcb, (float*)d_out, B, T);
}

// round 8
// speedup vs baseline: 1.2097x; 1.2097x over previous
#include <cuda_runtime.h>
#include <cstddef>

// 2-layer LSTM (H=20) + FC head, B=4096, T=512, D=1.
// Restructured: lane = sequence (32 seqs/block of 256 thr), warp = 5 gate-pairs.
// Weight loads are warp-UNIFORM (broadcast, 1 wavefront) -- kills the 4x
// crossbar waste of all previous rounds. Gates exchanged via shared; cell
// update round-robin over warps with c-state in registers.

using u64 = unsigned long long;

__device__ __forceinline__ u64 fma2(u64 a, u64 b, u64 c) {
    u64 d;
    asm("fma.rn.f32x2 %0, %1, %2, %3;" : "=l"(d) : "l"(a), "l"(b), "l"(c));
    return d;
}
__device__ __forceinline__ u64 pk2(float lo, float hi) {
    u64 r;
    asm("mov.b64 %0, {%1, %2};" : "=l"(r) : "f"(lo), "f"(hi));
    return r;
}
__device__ __forceinline__ void up2(float& lo, float& hi, u64 v) {
    asm("mov.b64 {%0, %1}, %2;" : "=f"(lo), "=f"(hi) : "l"(v));
}
__device__ __forceinline__ float ex2_(float x) {
    float y; asm("ex2.approx.f32 %0, %1;" : "=f"(y) : "f"(x)); return y;
}
__device__ __forceinline__ float rcp_(float x) {
    float y; asm("rcp.approx.f32 %0, %1;" : "=f"(y) : "f"(x)); return y;
}

#define L2E 1.4426950408889634f

__device__ __forceinline__ float sigm_(float x) {
    return rcp_(1.0f + ex2_(-L2E * x));
}
__device__ __forceinline__ float tanh_(float x) {
    return fmaf(2.0f, rcp_(1.0f + ex2_(-2.0f * L2E * x)), -1.0f);
}

// pair p in [0,40): p<20 -> rows (p, 20+p) = (i,f) of unit p
//                   p>=20 -> rows (40+j, 60+j) = (g,o) of unit j=p-20
__global__ void __launch_bounds__(256, 1) lstm2_fc_kernel(
    const float* __restrict__ x,     // [B, T]
    const float* __restrict__ Wih0,  // [80, 1]
    const float* __restrict__ Whh0,  // [80, 20]
    const float* __restrict__ bih0,  // [80]
    const float* __restrict__ bhh0,  // [80]
    const float* __restrict__ Wih1,  // [80, 20]
    const float* __restrict__ Whh1,  // [80, 20]
    const float* __restrict__ bih1,  // [80]
    const float* __restrict__ bhh1,  // [80]
    const float* __restrict__ fcW,   // [1, 20]
    const float* __restrict__ fcb,   // [1]
    float* __restrict__ out,         // [B, 1]
    int Btot, int Tlen)
{
    __shared__ __align__(16) u64 w0s[40 * 20];   // pair-packed Whh0
    __shared__ __align__(16) u64 w1s[40 * 40];   // pair-packed [Wih1|Whh1]
    __shared__ __align__(16) u64 wxs[40], b0s[40], b1s[40];
    __shared__ __align__(16) u64 gsh[40 * 32];   // gates, reused for both layers
    __shared__ __align__(16) float h0s[20 * 32];
    __shared__ __align__(16) float h1s[20 * 32];
    __shared__ __align__(16) float xs[32 * 32];  // [tt][seq] tile of x

    const int tid = threadIdx.x;

    // ---- pack weights (pair layout) ----
    for (int idx = tid; idx < 800; idx += 256) {
        int p = idx / 20, m = idx % 20;
        int j = (p < 20) ? p : (p - 20);
        int rlo = (p < 20) ? j : (40 + j);
        int rhi = rlo + 20;
        w0s[p * 20 + m] = pk2(Whh0[rlo * 20 + m], Whh0[rhi * 20 + m]);
    }
    for (int idx = tid; idx < 1600; idx += 256) {
        int p = idx / 40, mm = idx % 40;
        int j = (p < 20) ? p : (p - 20);
        int rlo = (p < 20) ? j : (40 + j);
        int rhi = rlo + 20;
        const float* mat = (mm < 20) ? Wih1 : Whh1;
        int m = (mm < 20) ? mm : (mm - 20);
        w1s[p * 40 + mm] = pk2(mat[rlo * 20 + m], mat[rhi * 20 + m]);
    }
    for (int p = tid; p < 40; p += 256) {
        int j = (p < 20) ? p : (p - 20);
        int rlo = (p < 20) ? j : (40 + j);
        int rhi = rlo + 20;
        wxs[p] = pk2(Wih0[rlo], Wih0[rhi]);
        b0s[p] = pk2(bih0[rlo] + bhh0[rlo], bih0[rhi] + bhh0[rhi]);
        b1s[p] = pk2(bih1[rlo] + bhh1[rlo], bih1[rhi] + bhh1[rhi]);
    }
    for (int idx = tid; idx < 640; idx += 256) { h0s[idx] = 0.f; h1s[idx] = 0.f; }
    __syncthreads();

    const int u  = tid >> 5;    // warp: pair-group / unit-group
    const int s  = tid & 31;    // lane = sequence within block
    const int pb = u * 5;       // first pair owned by this warp
    const int b0g = blockIdx.x * 32;

    // hoist per-warp pair scalars to registers (uniform across lanes)
    u64 wxp[5], b0p[5], b1p[5];
    #pragma unroll
    for (int k = 0; k < 5; ++k) {
        wxp[k] = wxs[pb + k];
        b0p[k] = b0s[pb + k];
        b1p[k] = b1s[pb + k];
    }

    // cell state for owned units j = u + 8*jj (j < 20)
    float c0[3] = {0.f, 0.f, 0.f};
    float c1[3] = {0.f, 0.f, 0.f};

    #pragma unroll 1
    for (int t = 0; t < Tlen; ++t) {
        const int tt = t & 31;
        if (tt == 0) {
            // stage next 32 timesteps of x for our 32 sequences
            int sq = tid >> 3, i0 = (tid & 7) * 4;
            int bb = b0g + sq;
            const float* xrow = x + (size_t)((bb < Btot) ? bb : (Btot - 1)) * Tlen;
            #pragma unroll
            for (int i = 0; i < 4; ++i) {
                int tg = t + i0 + i;
                xs[(i0 + i) * 32 + sq] = (tg < Tlen && bb < Btot) ? __ldg(&xrow[tg]) : 0.f;
            }
            __syncthreads();
        }

        // ================= matvec layer 0 =================
        {
            float xt = xs[tt * 32 + s];
            u64 xt2 = pk2(xt, xt);
            u64 acc[5];
            #pragma unroll
            for (int k = 0; k < 5; ++k) acc[k] = fma2(wxp[k], xt2, b0p[k]);
            #pragma unroll
            for (int m2 = 0; m2 < 10; ++m2) {
                float ha = h0s[(2 * m2) * 32 + s];
                float hc = h0s[(2 * m2 + 1) * 32 + s];
                u64 h2a = pk2(ha, ha), h2b = pk2(hc, hc);
                #pragma unroll
                for (int k = 0; k < 5; ++k) {
                    ulonglong2 w = *reinterpret_cast<const ulonglong2*>(&w0s[(pb + k) * 20 + 2 * m2]);
                    acc[k] = fma2(w.x, h2a, acc[k]);
                    acc[k] = fma2(w.y, h2b, acc[k]);
                }
            }
            #pragma unroll
            for (int k = 0; k < 5; ++k) gsh[(pb + k) * 32 + s] = acc[k];
        }
        __syncthreads();

        // ================= cell layer 0 =================
        #pragma unroll
        for (int jj = 0; jj < 3; ++jj) {
            int j = u + 8 * jj;
            if (j < 20) {
                float gi, gf, gg, go;
                up2(gi, gf, gsh[j * 32 + s]);
                up2(gg, go, gsh[(20 + j) * 32 + s]);
                float ai = sigm_(gi), af = sigm_(gf);
                float ag = tanh_(gg), ao = sigm_(go);
                float cn = fmaf(af, c0[jj], ai * ag);
                c0[jj] = cn;
                h0s[j * 32 + s] = ao * tanh_(cn);
            }
        }
        __syncthreads();

        // ================= matvec layer 1 =================
        {
            u64 acc[5];
            #pragma unroll
            for (int k = 0; k < 5; ++k) acc[k] = b1p[k];
            #pragma unroll
            for (int m2 = 0; m2 < 10; ++m2) {
                float ha = h0s[(2 * m2) * 32 + s];
                float hc = h0s[(2 * m2 + 1) * 32 + s];
                u64 h2a = pk2(ha, ha), h2b = pk2(hc, hc);
                #pragma unroll
                for (int k = 0; k < 5; ++k) {
                    ulonglong2 w = *reinterpret_cast<const ulonglong2*>(&w1s[(pb + k) * 40 + 2 * m2]);
                    acc[k] = fma2(w.x, h2a, acc[k]);
                    acc[k] = fma2(w.y, h2b, acc[k]);
                }
            }
            #pragma unroll
            for (int m2 = 0; m2 < 10; ++m2) {
                float ha = h1s[(2 * m2) * 32 + s];
                float hc = h1s[(2 * m2 + 1) * 32 + s];
                u64 h2a = pk2(ha, ha), h2b = pk2(hc, hc);
                #pragma unroll
                for (int k = 0; k < 5; ++k) {
                    ulonglong2 w = *reinterpret_cast<const ulonglong2*>(&w1s[(pb + k) * 40 + 20 + 2 * m2]);
                    acc[k] = fma2(w.x, h2a, acc[k]);
                    acc[k] = fma2(w.y, h2b, acc[k]);
                }
            }
            #pragma unroll
            for (int k = 0; k < 5; ++k) gsh[(pb + k) * 32 + s] = acc[k];
        }
        __syncthreads();

        // ================= cell layer 1 =================
        #pragma unroll
        for (int jj = 0; jj < 3; ++jj) {
            int j = u + 8 * jj;
            if (j < 20) {
                float gi, gf, gg, go;
                up2(gi, gf, gsh[j * 32 + s]);
                up2(gg, go, gsh[(20 + j) * 32 + s]);
                float ai = sigm_(gi), af = sigm_(gf);
                float ag = tanh_(gg), ao = sigm_(go);
                float cn = fmaf(af, c1[jj], ai * ag);
                c1[jj] = cn;
                h1s[j * 32 + s] = ao * tanh_(cn);
            }
        }
        __syncthreads();
    }

    // ---- FC head: h1s holds final h1 ----
    if (tid < 32) {
        float acc = __ldg(&fcb[0]);
        #pragma unroll
        for (int j = 0; j < 20; ++j)
            acc = fmaf(__ldg(&fcW[j]), h1s[j * 32 + tid], acc);
        int bo = b0g + tid;
        if (bo < Btot) out[bo] = acc;
    }
}

extern "C" void kernel_launch(void* const* d_in, const int* in_sizes, int n_in,
                              void* d_out, int out_size)
{
    const float* x    = (const float*)d_in[0];
    const float* Wih0 = (const float*)d_in[1];
    const float* Whh0 = (const float*)d_in[2];
    const float* bih0 = (const float*)d_in[3];
    const float* bhh0 = (const float*)d_in[4];
    const float* Wih1 = (const float*)d_in[5];
    const float* Whh1 = (const float*)d_in[6];
    const float* bih1 = (const float*)d_in[7];
    const float* bhh1 = (const float*)d_in[8];
    const float* fcW  = (const float*)d_in[9];
    const float* fcb  = (const float*)d_in[10];

    const int B = out_size;              // out is [B, 1] fp32
    const int T = in_sizes[0] / B;       // x is [B, T, 1]
    const int blocks = (B + 31) / 32;    // 32 seqs per 256-thread block

    lstm2_fc_kernel<<<blocks, 256>>>(x, Wih0, Whh0, bih0, bhh0,
                                     Wih1, Whh1, bih1, bhh1,
                                     fcW, fcb, (float*)d_out, B, T);
}

// round 9
// speedup vs baseline: 1.2791x; 1.0573x over previous
#include <cuda_runtime.h>
#include <cstddef>

// 2-layer LSTM (H=20) + FC head, B=4096, T=512, D=1.
// Lane = sequence (32 seqs / 256-thread block), warp = 5 gate-pairs,
// warp-uniform weight loads (broadcast LDS). Software-pipelined across layers:
//   Phase M: gates1(t) AND gates0(t+1) together (independent given h0(t))
//   Phase C: cell1(t) [warps 0-3] AND cell0(t+1) [warps 4-7]
// => 2 barriers per timestep instead of 4, 2x per-phase ILP.

using u64 = unsigned long long;

__device__ __forceinline__ u64 fma2(u64 a, u64 b, u64 c) {
    u64 d;
    asm("fma.rn.f32x2 %0, %1, %2, %3;" : "=l"(d) : "l"(a), "l"(b), "l"(c));
    return d;
}
__device__ __forceinline__ u64 pk2(float lo, float hi) {
    u64 r;
    asm("mov.b64 %0, {%1, %2};" : "=l"(r) : "f"(lo), "f"(hi));
    return r;
}
__device__ __forceinline__ void up2(float& lo, float& hi, u64 v) {
    asm("mov.b64 {%0, %1}, %2;" : "=f"(lo), "=f"(hi) : "l"(v));
}
__device__ __forceinline__ float ex2_(float x) {
    float y; asm("ex2.approx.f32 %0, %1;" : "=f"(y) : "f"(x)); return y;
}
__device__ __forceinline__ float rcp_(float x) {
    float y; asm("rcp.approx.f32 %0, %1;" : "=f"(y) : "f"(x)); return y;
}

#define L2E 1.4426950408889634f

__device__ __forceinline__ float sigm_(float x) {
    return rcp_(1.0f + ex2_(-L2E * x));
}
__device__ __forceinline__ float tanh_(float x) {
    return fmaf(2.0f, rcp_(1.0f + ex2_(-2.0f * L2E * x)), -1.0f);
}

// pair p in [0,40): p<20 -> rows (p, 20+p) = (i,f) of unit p
//                   p>=20 -> rows (40+j, 60+j) = (g,o) of unit j=p-20
__global__ void __launch_bounds__(256, 1) lstm2_fc_kernel(
    const float* __restrict__ x,     // [B, T]
    const float* __restrict__ Wih0,  // [80, 1]
    const float* __restrict__ Whh0,  // [80, 20]
    const float* __restrict__ bih0,  // [80]
    const float* __restrict__ bhh0,  // [80]
    const float* __restrict__ Wih1,  // [80, 20]
    const float* __restrict__ Whh1,  // [80, 20]
    const float* __restrict__ bih1,  // [80]
    const float* __restrict__ bhh1,  // [80]
    const float* __restrict__ fcW,   // [1, 20]
    const float* __restrict__ fcb,   // [1]
    float* __restrict__ out,         // [B, 1]
    int Btot, int Tlen)
{
    __shared__ __align__(16) u64 w0s[40 * 20];   // pair-packed Whh0
    __shared__ __align__(16) u64 w1s[40 * 40];   // pair-packed [Wih1 | Whh1]
    __shared__ __align__(16) u64 wxs[40], b0s[40], b1s[40];
    __shared__ __align__(16) u64 gsh0[40 * 32];  // layer0 gates (for step t+1)
    __shared__ __align__(16) u64 gsh1[40 * 32];  // layer1 gates (for step t)
    __shared__ __align__(16) float h0s[20 * 32];
    __shared__ __align__(16) float h1s[20 * 32];
    __shared__ __align__(16) float xs[32 * 32];  // [tt][seq] tile of x

    const int tid = threadIdx.x;

    // ---- pack weights (pair layout) ----
    for (int idx = tid; idx < 800; idx += 256) {
        int p = idx / 20, m = idx % 20;
        int j = (p < 20) ? p : (p - 20);
        int rlo = (p < 20) ? j : (40 + j);
        int rhi = rlo + 20;
        w0s[p * 20 + m] = pk2(Whh0[rlo * 20 + m], Whh0[rhi * 20 + m]);
    }
    for (int idx = tid; idx < 1600; idx += 256) {
        int p = idx / 40, mm = idx % 40;
        int j = (p < 20) ? p : (p - 20);
        int rlo = (p < 20) ? j : (40 + j);
        int rhi = rlo + 20;
        const float* mat = (mm < 20) ? Wih1 : Whh1;
        int m = (mm < 20) ? mm : (mm - 20);
        w1s[p * 40 + mm] = pk2(mat[rlo * 20 + m], mat[rhi * 20 + m]);
    }
    for (int p = tid; p < 40; p += 256) {
        int j = (p < 20) ? p : (p - 20);
        int rlo = (p < 20) ? j : (40 + j);
        int rhi = rlo + 20;
        wxs[p] = pk2(Wih0[rlo], Wih0[rhi]);
        b0s[p] = pk2(bih0[rlo] + bhh0[rlo], bih0[rhi] + bhh0[rhi]);
        b1s[p] = pk2(bih1[rlo] + bhh1[rlo], bih1[rhi] + bhh1[rhi]);
    }
    for (int idx = tid; idx < 640; idx += 256) { h0s[idx] = 0.f; h1s[idx] = 0.f; }

    const int u  = tid >> 5;    // warp index
    const int s  = tid & 31;    // lane = sequence within block
    const int pb = u * 5;       // first pair owned for matvec
    const int b0g = blockIdx.x * 32;

    // ---- stage x tile [0,32) ----
    {
        int sq = tid >> 3, i0 = (tid & 7) * 4;
        int bb = b0g + sq;
        const float* xrow = x + (size_t)((bb < Btot) ? bb : (Btot - 1)) * Tlen;
        #pragma unroll
        for (int i = 0; i < 4; ++i) {
            int tg = i0 + i;
            xs[(i0 + i) * 32 + sq] = (tg < Tlen && bb < Btot) ? __ldg(&xrow[tg]) : 0.f;
        }
    }
    __syncthreads();

    // hoist per-warp pair scalars (uniform across lanes)
    u64 wxp[5], b0p[5], b1p[5];
    #pragma unroll
    for (int k = 0; k < 5; ++k) {
        wxp[k] = wxs[pb + k];
        b0p[k] = b0s[pb + k];
        b1p[k] = b1s[pb + k];
    }

    // cell state: warps 0-3 own c1 for units u*5..u*5+4; warps 4-7 own c0 for (u-4)*5..
    float cs[5] = {0.f, 0.f, 0.f, 0.f, 0.f};

    // ---- prologue: gates0(0) = Wih0*x(0) + b0 (h0(-1)=0) ----
    {
        float x0 = xs[0 * 32 + s];
        u64 x02 = pk2(x0, x0);
        #pragma unroll
        for (int k = 0; k < 5; ++k)
            gsh0[(pb + k) * 32 + s] = fma2(wxp[k], x02, b0p[k]);
    }
    __syncthreads();

    #pragma unroll 1
    for (int t = 0; t < Tlen; ++t) {
        // ================= PHASE C =================
        if (u >= 4) {
            // cell0(t): gsh0 -> h0(t)
            const int j0 = (u - 4) * 5;
            #pragma unroll
            for (int jl = 0; jl < 5; ++jl) {
                const int j = j0 + jl;
                float gi, gf, gg, go;
                up2(gi, gf, gsh0[j * 32 + s]);
                up2(gg, go, gsh0[(20 + j) * 32 + s]);
                float ai = sigm_(gi), af = sigm_(gf);
                float ag = tanh_(gg), ao = sigm_(go);
                float cn = fmaf(af, cs[jl], ai * ag);
                cs[jl] = cn;
                h0s[j * 32 + s] = ao * tanh_(cn);
            }
        } else if (t > 0) {
            // cell1(t-1): gsh1 -> h1(t-1)
            const int j0 = u * 5;
            #pragma unroll
            for (int jl = 0; jl < 5; ++jl) {
                const int j = j0 + jl;
                float gi, gf, gg, go;
                up2(gi, gf, gsh1[j * 32 + s]);
                up2(gg, go, gsh1[(20 + j) * 32 + s]);
                float ai = sigm_(gi), af = sigm_(gf);
                float ag = tanh_(gg), ao = sigm_(go);
                float cn = fmaf(af, cs[jl], ai * ag);
                cs[jl] = cn;
                h1s[j * 32 + s] = ao * tanh_(cn);
            }
        }
        __syncthreads();

        // stage next x tile when phase M is about to cross into it
        if (((t + 1) & 31) == 0 && (t + 1) < Tlen) {
            int sq = tid >> 3, i0 = (tid & 7) * 4;
            int bb = b0g + sq;
            const float* xrow = x + (size_t)((bb < Btot) ? bb : (Btot - 1)) * Tlen;
            #pragma unroll
            for (int i = 0; i < 4; ++i) {
                int tg = t + 1 + i0 + i;
                xs[(i0 + i) * 32 + sq] = (tg < Tlen && bb < Btot) ? __ldg(&xrow[tg]) : 0.f;
            }
            __syncthreads();
        }

        // ================= PHASE M =================
        // gates1(t) from {h0(t), h1(t-1)}  AND  gates0(t+1) from {x(t+1), h0(t)}
        {
            float xt = (t + 1 < Tlen) ? xs[((t + 1) & 31) * 32 + s] : 0.f;
            u64 xt2 = pk2(xt, xt);
            u64 a1[5], a0[5];
            #pragma unroll
            for (int k = 0; k < 5; ++k) {
                a1[k] = b1p[k];
                a0[k] = fma2(wxp[k], xt2, b0p[k]);
            }
            #pragma unroll
            for (int m2 = 0; m2 < 10; ++m2) {
                float ha = h0s[(2 * m2) * 32 + s];
                float hb = h0s[(2 * m2 + 1) * 32 + s];
                u64 h2a = pk2(ha, ha), h2b = pk2(hb, hb);
                #pragma unroll
                for (int k = 0; k < 5; ++k) {
                    ulonglong2 wu = *reinterpret_cast<const ulonglong2*>(&w1s[(pb + k) * 40 + 2 * m2]);
                    ulonglong2 w0 = *reinterpret_cast<const ulonglong2*>(&w0s[(pb + k) * 20 + 2 * m2]);
                    a1[k] = fma2(wu.x, h2a, a1[k]);
                    a1[k] = fma2(wu.y, h2b, a1[k]);
                    a0[k] = fma2(w0.x, h2a, a0[k]);
                    a0[k] = fma2(w0.y, h2b, a0[k]);
                }
            }
            #pragma unroll
            for (int m2 = 0; m2 < 10; ++m2) {
                float ha = h1s[(2 * m2) * 32 + s];
                float hb = h1s[(2 * m2 + 1) * 32 + s];
                u64 h2a = pk2(ha, ha), h2b = pk2(hb, hb);
                #pragma unroll
                for (int k = 0; k < 5; ++k) {
                    ulonglong2 wv = *reinterpret_cast<const ulonglong2*>(&w1s[(pb + k) * 40 + 20 + 2 * m2]);
                    a1[k] = fma2(wv.x, h2a, a1[k]);
                    a1[k] = fma2(wv.y, h2b, a1[k]);
                }
            }
            #pragma unroll
            for (int k = 0; k < 5; ++k) {
                gsh1[(pb + k) * 32 + s] = a1[k];
                gsh0[(pb + k) * 32 + s] = a0[k];
            }
        }
        __syncthreads();
    }

    // ---- epilogue: cell1(T-1) -> h1(T-1) ----
    if (u < 4) {
        const int j0 = u * 5;
        #pragma unroll
        for (int jl = 0; jl < 5; ++jl) {
            const int j = j0 + jl;
            float gi, gf, gg, go;
            up2(gi, gf, gsh1[j * 32 + s]);
            up2(gg, go, gsh1[(20 + j) * 32 + s]);
            float ai = sigm_(gi), af = sigm_(gf);
            float ag = tanh_(gg), ao = sigm_(go);
            float cn = fmaf(af, cs[jl], ai * ag);
            cs[jl] = cn;
            h1s[j * 32 + s] = ao * tanh_(cn);
        }
    }
    __syncthreads();

    // ---- FC head ----
    if (tid < 32) {
        float acc = __ldg(&fcb[0]);
        #pragma unroll
        for (int j = 0; j < 20; ++j)
            acc = fmaf(__ldg(&fcW[j]), h1s[j * 32 + tid], acc);
        int bo = b0g + tid;
        if (bo < Btot) out[bo] = acc;
    }
}

extern "C" void kernel_launch(void* const* d_in, const int* in_sizes, int n_in,
                              void* d_out, int out_size)
{
    const float* x    = (const float*)d_in[0];
    const float* Wih0 = (const float*)d_in[1];
    const float* Whh0 = (const float*)d_in[2];
    const float* bih0 = (const float*)d_in[3];
    const float* bhh0 = (const float*)d_in[4];
    const float* Wih1 = (const float*)d_in[5];
    const float* Whh1 = (const float*)d_in[6];
    const float* bih1 = (const float*)d_in[7];
    const float* bhh1 = (const float*)d_in[8];
    const float* fcW  = (const float*)d_in[9];
    const float* fcb  = (const float*)d_in[10];

    const int B = out_size;              // out is [B, 1] fp32
    const int T = in_sizes[0] / B;       // x is [B, T, 1]
    const int blocks = (B + 31) / 32;    // 32 seqs per 256-thread block

    lstm2_fc_kernel<<<blocks, 256>>>(x, Wih0, Whh0, bih0, bhh0,
                                     Wih1, Whh1, bih1, bhh1,
                                     fcW, fcb, (float*)d_out, B, T);
}

// round 10
// speedup vs baseline: 1.2882x; 1.0071x over previous
#include <cuda_runtime.h>
#include <cstddef>

// 2-layer LSTM (H=20) + FC head, B=4096, T=512, D=1.
// Lane = sequence (32 seqs / block), 512 threads = 16 warps (4/SMSP).
// Phase M split across warp halves:
//   warps 0-7 : gates1(t)   (5 pairs each; reads h0(t), h1(t-1))
//   warps 8-15: gates0(t+1) (5 pairs each; reads x(t+1), h0(t))
// Phase C: warps 8-11 cell0(t) ; warps 0-3 cell1(t-1). 2 barriers/step.

using u64 = unsigned long long;

__device__ __forceinline__ u64 fma2(u64 a, u64 b, u64 c) {
    u64 d;
    asm("fma.rn.f32x2 %0, %1, %2, %3;" : "=l"(d) : "l"(a), "l"(b), "l"(c));
    return d;
}
__device__ __forceinline__ u64 pk2(float lo, float hi) {
    u64 r;
    asm("mov.b64 %0, {%1, %2};" : "=l"(r) : "f"(lo), "f"(hi));
    return r;
}
__device__ __forceinline__ void up2(float& lo, float& hi, u64 v) {
    asm("mov.b64 {%0, %1}, %2;" : "=f"(lo), "=f"(hi) : "l"(v));
}
__device__ __forceinline__ float ex2_(float x) {
    float y; asm("ex2.approx.f32 %0, %1;" : "=f"(y) : "f"(x)); return y;
}
__device__ __forceinline__ float rcp_(float x) {
    float y; asm("rcp.approx.f32 %0, %1;" : "=f"(y) : "f"(x)); return y;
}

#define L2E 1.4426950408889634f

__device__ __forceinline__ float sigm_(float x) {
    return rcp_(1.0f + ex2_(-L2E * x));
}
__device__ __forceinline__ float tanh_(float x) {
    return fmaf(2.0f, rcp_(1.0f + ex2_(-2.0f * L2E * x)), -1.0f);
}

// pair p in [0,40): p<20 -> rows (p, 20+p) = (i,f) of unit p
//                   p>=20 -> rows (40+j, 60+j) = (g,o) of unit j=p-20
__global__ void __launch_bounds__(512, 1) lstm2_fc_kernel(
    const float* __restrict__ x,     // [B, T]
    const float* __restrict__ Wih0,  // [80, 1]
    const float* __restrict__ Whh0,  // [80, 20]
    const float* __restrict__ bih0,  // [80]
    const float* __restrict__ bhh0,  // [80]
    const float* __restrict__ Wih1,  // [80, 20]
    const float* __restrict__ Whh1,  // [80, 20]
    const float* __restrict__ bih1,  // [80]
    const float* __restrict__ bhh1,  // [80]
    const float* __restrict__ fcW,   // [1, 20]
    const float* __restrict__ fcb,   // [1]
    float* __restrict__ out,         // [B, 1]
    int Btot, int Tlen)
{
    __shared__ __align__(16) u64 w0s[40 * 20];   // pair-packed Whh0
    __shared__ __align__(16) u64 w1s[40 * 40];   // pair-packed [Wih1 | Whh1]
    __shared__ __align__(16) u64 wxs[40], b0s[40], b1s[40];
    __shared__ __align__(16) u64 gsh0[40 * 32];  // layer0 gates (for step t+1)
    __shared__ __align__(16) u64 gsh1[40 * 32];  // layer1 gates (for step t)
    __shared__ __align__(16) float h0s[20 * 32];
    __shared__ __align__(16) float h1s[20 * 32];
    __shared__ __align__(16) float xs[32 * 32];  // [tt][seq] tile of x

    const int tid = threadIdx.x;

    // ---- pack weights (pair layout) ----
    for (int idx = tid; idx < 800; idx += 512) {
        int p = idx / 20, m = idx % 20;
        int j = (p < 20) ? p : (p - 20);
        int rlo = (p < 20) ? j : (40 + j);
        int rhi = rlo + 20;
        w0s[p * 20 + m] = pk2(Whh0[rlo * 20 + m], Whh0[rhi * 20 + m]);
    }
    for (int idx = tid; idx < 1600; idx += 512) {
        int p = idx / 40, mm = idx % 40;
        int j = (p < 20) ? p : (p - 20);
        int rlo = (p < 20) ? j : (40 + j);
        int rhi = rlo + 20;
        const float* mat = (mm < 20) ? Wih1 : Whh1;
        int m = (mm < 20) ? mm : (mm - 20);
        w1s[p * 40 + mm] = pk2(mat[rlo * 20 + m], mat[rhi * 20 + m]);
    }
    for (int p = tid; p < 40; p += 512) {
        int j = (p < 20) ? p : (p - 20);
        int rlo = (p < 20) ? j : (40 + j);
        int rhi = rlo + 20;
        wxs[p] = pk2(Wih0[rlo], Wih0[rhi]);
        b0s[p] = pk2(bih0[rlo] + bhh0[rlo], bih0[rhi] + bhh0[rhi]);
        b1s[p] = pk2(bih1[rlo] + bhh1[rlo], bih1[rhi] + bhh1[rhi]);
    }
    for (int idx = tid; idx < 640; idx += 512) { h0s[idx] = 0.f; h1s[idx] = 0.f; }

    const int u  = tid >> 5;       // warp index 0..15
    const int s  = tid & 31;       // lane = sequence within block
    const bool isG1 = (u < 8);     // gates1 warps, else gates0 warps
    const int pb = (u & 7) * 5;    // first pair owned in phase M
    const int b0g = blockIdx.x * 32;

    // ---- stage x tile [0,32) : 512 threads, 2 elems each ----
    {
        int sq = tid >> 4, i0 = (tid & 15) * 2;
        int bb = b0g + sq;
        const float* xrow = x + (size_t)((bb < Btot) ? bb : (Btot - 1)) * Tlen;
        #pragma unroll
        for (int i = 0; i < 2; ++i) {
            int tg = i0 + i;
            xs[(i0 + i) * 32 + sq] = (tg < Tlen && bb < Btot) ? __ldg(&xrow[tg]) : 0.f;
        }
    }
    __syncthreads();

    // hoist per-warp pair scalars (uniform across lanes)
    u64 wxp[5], bp[5];
    #pragma unroll
    for (int k = 0; k < 5; ++k) {
        wxp[k] = wxs[pb + k];                       // used by G0 warps only
        bp[k]  = isG1 ? b1s[pb + k] : b0s[pb + k];  // bias for owned matvec
    }

    // cell state: warps 8-11 own c0 (units (u-8)*5..), warps 0-3 own c1 (units u*5..)
    float cs[5] = {0.f, 0.f, 0.f, 0.f, 0.f};

    // ---- prologue: gates0(0) = Wih0*x(0) + b0 (h0(-1)=0), G0 warps ----
    if (!isG1) {
        float x0 = xs[0 * 32 + s];
        u64 x02 = pk2(x0, x0);
        #pragma unroll
        for (int k = 0; k < 5; ++k)
            gsh0[(pb + k) * 32 + s] = fma2(wxp[k], x02, bp[k]);
    }
    __syncthreads();

    #pragma unroll 1
    for (int t = 0; t < Tlen; ++t) {
        // ================= PHASE C =================
        if (u >= 8 && u < 12) {
            // cell0(t): gsh0 -> h0(t)
            const int j0 = (u - 8) * 5;
            #pragma unroll
            for (int jl = 0; jl < 5; ++jl) {
                const int j = j0 + jl;
                float gi, gf, gg, go;
                up2(gi, gf, gsh0[j * 32 + s]);
                up2(gg, go, gsh0[(20 + j) * 32 + s]);
                float ai = sigm_(gi), af = sigm_(gf);
                float ag = tanh_(gg), ao = sigm_(go);
                float cn = fmaf(af, cs[jl], ai * ag);
                cs[jl] = cn;
                h0s[j * 32 + s] = ao * tanh_(cn);
            }
        } else if (u < 4 && t > 0) {
            // cell1(t-1): gsh1 -> h1(t-1)
            const int j0 = u * 5;
            #pragma unroll
            for (int jl = 0; jl < 5; ++jl) {
                const int j = j0 + jl;
                float gi, gf, gg, go;
                up2(gi, gf, gsh1[j * 32 + s]);
                up2(gg, go, gsh1[(20 + j) * 32 + s]);
                float ai = sigm_(gi), af = sigm_(gf);
                float ag = tanh_(gg), ao = sigm_(go);
                float cn = fmaf(af, cs[jl], ai * ag);
                cs[jl] = cn;
                h1s[j * 32 + s] = ao * tanh_(cn);
            }
        }
        __syncthreads();

        // stage next x tile when needed
        if (((t + 1) & 31) == 0 && (t + 1) < Tlen) {
            int sq = tid >> 4, i0 = (tid & 15) * 2;
            int bb = b0g + sq;
            const float* xrow = x + (size_t)((bb < Btot) ? bb : (Btot - 1)) * Tlen;
            #pragma unroll
            for (int i = 0; i < 2; ++i) {
                int tg = t + 1 + i0 + i;
                xs[(i0 + i) * 32 + sq] = (tg < Tlen && bb < Btot) ? __ldg(&xrow[tg]) : 0.f;
            }
            __syncthreads();
        }

        // ================= PHASE M =================
        if (isG1) {
            // gates1(t) from {h0(t), h1(t-1)}
            u64 a1[5];
            #pragma unroll
            for (int k = 0; k < 5; ++k) a1[k] = bp[k];
            #pragma unroll
            for (int m2 = 0; m2 < 10; ++m2) {
                float ha = h0s[(2 * m2) * 32 + s];
                float hb = h0s[(2 * m2 + 1) * 32 + s];
                u64 h2a = pk2(ha, ha), h2b = pk2(hb, hb);
                #pragma unroll
                for (int k = 0; k < 5; ++k) {
                    ulonglong2 wu = *reinterpret_cast<const ulonglong2*>(&w1s[(pb + k) * 40 + 2 * m2]);
                    a1[k] = fma2(wu.x, h2a, a1[k]);
                    a1[k] = fma2(wu.y, h2b, a1[k]);
                }
            }
            #pragma unroll
            for (int m2 = 0; m2 < 10; ++m2) {
                float ha = h1s[(2 * m2) * 32 + s];
                float hb = h1s[(2 * m2 + 1) * 32 + s];
                u64 h2a = pk2(ha, ha), h2b = pk2(hb, hb);
                #pragma unroll
                for (int k = 0; k < 5; ++k) {
                    ulonglong2 wv = *reinterpret_cast<const ulonglong2*>(&w1s[(pb + k) * 40 + 20 + 2 * m2]);
                    a1[k] = fma2(wv.x, h2a, a1[k]);
                    a1[k] = fma2(wv.y, h2b, a1[k]);
                }
            }
            #pragma unroll
            for (int k = 0; k < 5; ++k) gsh1[(pb + k) * 32 + s] = a1[k];
        } else {
            // gates0(t+1) from {x(t+1), h0(t)}
            float xt = (t + 1 < Tlen) ? xs[((t + 1) & 31) * 32 + s] : 0.f;
            u64 xt2 = pk2(xt, xt);
            u64 a0[5];
            #pragma unroll
            for (int k = 0; k < 5; ++k) a0[k] = fma2(wxp[k], xt2, bp[k]);
            #pragma unroll
            for (int m2 = 0; m2 < 10; ++m2) {
                float ha = h0s[(2 * m2) * 32 + s];
                float hb = h0s[(2 * m2 + 1) * 32 + s];
                u64 h2a = pk2(ha, ha), h2b = pk2(hb, hb);
                #pragma unroll
                for (int k = 0; k < 5; ++k) {
                    ulonglong2 w0 = *reinterpret_cast<const ulonglong2*>(&w0s[(pb + k) * 20 + 2 * m2]);
                    a0[k] = fma2(w0.x, h2a, a0[k]);
                    a0[k] = fma2(w0.y, h2b, a0[k]);
                }
            }
            #pragma unroll
            for (int k = 0; k < 5; ++k) gsh0[(pb + k) * 32 + s] = a0[k];
        }
        __syncthreads();
    }

    // ---- epilogue: cell1(T-1) -> h1(T-1), warps 0-3 ----
    if (u < 4) {
        const int j0 = u * 5;
        #pragma unroll
        for (int jl = 0; jl < 5; ++jl) {
            const int j = j0 + jl;
            float gi, gf, gg, go;
            up2(gi, gf, gsh1[j * 32 + s]);
            up2(gg, go, gsh1[(20 + j) * 32 + s]);
            float ai = sigm_(gi), af = sigm_(gf);
            float ag = tanh_(gg), ao = sigm_(go);
            float cn = fmaf(af, cs[jl], ai * ag);
            cs[jl] = cn;
            h1s[j * 32 + s] = ao * tanh_(cn);
        }
    }
    __syncthreads();

    // ---- FC head ----
    if (tid < 32) {
        float acc = __ldg(&fcb[0]);
        #pragma unroll
        for (int j = 0; j < 20; ++j)
            acc = fmaf(__ldg(&fcW[j]), h1s[j * 32 + tid], acc);
        int bo = b0g + tid;
        if (bo < Btot) out[bo] = acc;
    }
}

extern "C" void kernel_launch(void* const* d_in, const int* in_sizes, int n_in,
                              void* d_out, int out_size)
{
    const float* x    = (const float*)d_in[0];
    const float* Wih0 = (const float*)d_in[1];
    const float* Whh0 = (const float*)d_in[2];
    const float* bih0 = (const float*)d_in[3];
    const float* bhh0 = (const float*)d_in[4];
    const float* Wih1 = (const float*)d_in[5];
    const float* Whh1 = (const float*)d_in[6];
    const float* bih1 = (const float*)d_in[7];
    const float* bhh1 = (const float*)d_in[8];
    const float* fcW  = (const float*)d_in[9];
    const float* fcb  = (const float*)d_in[10];

    const int B = out_size;              // out is [B, 1] fp32
    const int T = in_sizes[0] / B;       // x is [B, T, 1]
    const int blocks = (B + 31) / 32;    // 32 seqs per 512-thread block

    lstm2_fc_kernel<<<blocks, 512>>>(x, Wih0, Whh0, bih0, bhh0,
                                     Wih1, Whh1, bih1, bhh1,
                                     fcW, fcb, (float*)d_out, B, T);
}

// round 11
// speedup vs baseline: 1.3915x; 1.0802x over previous
#include <cuda_runtime.h>
#include <cstddef>

// 2-layer LSTM (H=20) + FC head, B=4096, T=512, D=1.
// 512-thread block = TWO independent 256-thread pipelines (16 seqs each),
// each with its own named barrier -> C phase of one overlaps M phase of the
// other on the same SMSPs. Within a pipeline: half-warp = 16 seqs, the two
// halves of a warp own different gate-pairs. 2 named barriers per step.

using u64 = unsigned long long;

__device__ __forceinline__ u64 fma2(u64 a, u64 b, u64 c) {
    u64 d;
    asm("fma.rn.f32x2 %0, %1, %2, %3;" : "=l"(d) : "l"(a), "l"(b), "l"(c));
    return d;
}
__device__ __forceinline__ u64 pk2(float lo, float hi) {
    u64 r;
    asm("mov.b64 %0, {%1, %2};" : "=l"(r) : "f"(lo), "f"(hi));
    return r;
}
__device__ __forceinline__ void up2(float& lo, float& hi, u64 v) {
    asm("mov.b64 {%0, %1}, %2;" : "=f"(lo), "=f"(hi) : "l"(v));
}
__device__ __forceinline__ float ex2_(float x) {
    float y; asm("ex2.approx.f32 %0, %1;" : "=f"(y) : "f"(x)); return y;
}
__device__ __forceinline__ float rcp_(float x) {
    float y; asm("rcp.approx.f32 %0, %1;" : "=f"(y) : "f"(x)); return y;
}

#define L2E 1.4426950408889634f

__device__ __forceinline__ float sigm_(float x) {
    return rcp_(1.0f + ex2_(-L2E * x));
}
__device__ __forceinline__ float tanh_(float x) {
    return fmaf(2.0f, rcp_(1.0f + ex2_(-2.0f * L2E * x)), -1.0f);
}

// pipeline-scoped named barrier (ids 1 and 2; 0 reserved for __syncthreads)
#define PBAR(Pid) asm volatile("bar.sync %0, 256;" :: "r"((Pid) + 1) : "memory")

// pair p in [0,40): p<20 -> rows (p, 20+p) = (i,f) of unit p
//                   p>=20 -> rows (40+j, 60+j) = (g,o) of unit j=p-20
__global__ void __launch_bounds__(512, 1) lstm2_fc_kernel(
    const float* __restrict__ x,     // [B, T]
    const float* __restrict__ Wih0,  // [80, 1]
    const float* __restrict__ Whh0,  // [80, 20]
    const float* __restrict__ bih0,  // [80]
    const float* __restrict__ bhh0,  // [80]
    const float* __restrict__ Wih1,  // [80, 20]
    const float* __restrict__ Whh1,  // [80, 20]
    const float* __restrict__ bih1,  // [80]
    const float* __restrict__ bhh1,  // [80]
    const float* __restrict__ fcW,   // [1, 20]
    const float* __restrict__ fcb,   // [1]
    float* __restrict__ out,         // [B, 1]
    int Btot, int Tlen)
{
    __shared__ __align__(16) u64 w0s[40 * 20];   // pair-packed Whh0 (shared by pipes)
    __shared__ __align__(16) u64 w1s[40 * 40];   // pair-packed [Wih1 | Whh1]
    __shared__ __align__(16) u64 gsh0[2 * 40 * 16]; // per-pipe layer0 gates
    __shared__ __align__(16) u64 gsh1[2 * 40 * 16]; // per-pipe layer1 gates
    __shared__ __align__(16) float h0s[2 * 20 * 16];
    __shared__ __align__(16) float h1s[2 * 20 * 16];
    __shared__ __align__(16) float xs[2 * 16 * 16];  // per-pipe 16-step x tile

    const int tid = threadIdx.x;

    // ---- pack weights (pair layout), all 512 threads ----
    for (int idx = tid; idx < 800; idx += 512) {
        int p = idx / 20, m = idx % 20;
        int j = (p < 20) ? p : (p - 20);
        int rlo = (p < 20) ? j : (40 + j);
        int rhi = rlo + 20;
        w0s[p * 20 + m] = pk2(Whh0[rlo * 20 + m], Whh0[rhi * 20 + m]);
    }
    for (int idx = tid; idx < 1600; idx += 512) {
        int p = idx / 40, mm = idx % 40;
        int j = (p < 20) ? p : (p - 20);
        int rlo = (p < 20) ? j : (40 + j);
        int rhi = rlo + 20;
        const float* mat = (mm < 20) ? Wih1 : Whh1;
        int m = (mm < 20) ? mm : (mm - 20);
        w1s[p * 40 + mm] = pk2(mat[rlo * 20 + m], mat[rhi * 20 + m]);
    }
    for (int idx = tid; idx < 640; idx += 512) { h0s[idx] = 0.f; h1s[idx] = 0.f; }

    // ---- lane / pipeline mapping ----
    const int P    = tid >> 8;          // pipeline 0/1
    const int lt   = tid & 255;         // local tid within pipeline
    const int w8   = lt >> 5;           // warp-in-pipeline 0..7
    const int lane = tid & 31;
    const int half = lane >> 4;
    const int s16  = lane & 15;         // sequence within pipeline
    const bool isG1 = (w8 < 4);         // warps 0-3: gates1+cell1 ; 4-7: gates0+cell0
    const int hwm  = ((w8 & 3) << 1) | half;   // half-warp id 0..7
    const int pb   = hwm * 5;           // first pair owned in phase M
    const int b0g  = blockIdx.x * 32;
    const int sbase = b0g + P * 16;     // first seq of this pipeline

    // per-lane pair scalars from global (tiny, one-time)
    u64 wxp[5], bp[5];
    #pragma unroll
    for (int k = 0; k < 5; ++k) {
        int pp = pb + k;
        int j = (pp < 20) ? pp : (pp - 20);
        int rlo = (pp < 20) ? j : (40 + j);
        int rhi = rlo + 20;
        wxp[k] = pk2(__ldg(&Wih0[rlo]), __ldg(&Wih0[rhi]));
        bp[k] = isG1
            ? pk2(__ldg(&bih1[rlo]) + __ldg(&bhh1[rlo]), __ldg(&bih1[rhi]) + __ldg(&bhh1[rhi]))
            : pk2(__ldg(&bih0[rlo]) + __ldg(&bhh0[rlo]), __ldg(&bih0[rhi]) + __ldg(&bhh0[rhi]));
    }

    __syncthreads();   // weights packed, h zeroed (block-wide, once)

    // pipeline-local pointers
    u64*   g0 = &gsh0[P * 640];
    u64*   g1 = &gsh1[P * 640];
    float* h0 = &h0s[P * 320];
    float* h1 = &h1s[P * 320];
    float* xt_tile = &xs[P * 256];

    // ---- stage x tile [0,16) : 256 threads, 1 elem each ----
    {
        int sq = lt & 15, tt = lt >> 4;
        int bb = sbase + sq;
        const float* xrow = x + (size_t)((bb < Btot) ? bb : (Btot - 1)) * Tlen;
        xt_tile[tt * 16 + sq] = (tt < Tlen && bb < Btot) ? __ldg(&xrow[tt]) : 0.f;
    }
    PBAR(P);

    // cell state: warps 4-7 own c0, warps 0-3 own c1; units u = hwm + 8*jj (u<20)
    float cs[3] = {0.f, 0.f, 0.f};

    // ---- prologue: gates0(0) = Wih0*x(0) + b0 (h0(-1)=0), G0 warps ----
    if (!isG1) {
        float x0 = xt_tile[0 * 16 + s16];
        u64 x02 = pk2(x0, x0);
        #pragma unroll
        for (int k = 0; k < 5; ++k)
            g0[(pb + k) * 16 + s16] = fma2(wxp[k], x02, bp[k]);
    }
    PBAR(P);

    #pragma unroll 1
    for (int t = 0; t < Tlen; ++t) {
        // ================= PHASE C =================
        if (!isG1 || t > 0) {
            const u64*  gg = isG1 ? g1 : g0;   // cell1 reads gsh1, cell0 reads gsh0
            float*      hd = isG1 ? h1 : h0;
            #pragma unroll
            for (int jj = 0; jj < 3; ++jj) {
                int uu = hwm + 8 * jj;
                if (uu < 20) {
                    float gi, gf, ga, go;
                    up2(gi, gf, gg[uu * 16 + s16]);
                    up2(ga, go, gg[(20 + uu) * 16 + s16]);
                    float ai = sigm_(gi), af = sigm_(gf);
                    float ag = tanh_(ga), ao = sigm_(go);
                    float cn = fmaf(af, cs[jj], ai * ag);
                    cs[jj] = cn;
                    hd[uu * 16 + s16] = ao * tanh_(cn);
                }
            }
        }
        PBAR(P);

        // stage next x tile when M is about to cross into it
        if (((t + 1) & 15) == 0 && (t + 1) < Tlen) {
            int sq = lt & 15, tt = lt >> 4;
            int bb = sbase + sq;
            const float* xrow = x + (size_t)((bb < Btot) ? bb : (Btot - 1)) * Tlen;
            int tg = t + 1 + tt;
            xt_tile[tt * 16 + sq] = (tg < Tlen && bb < Btot) ? __ldg(&xrow[tg]) : 0.f;
            PBAR(P);
        }

        // ================= PHASE M =================
        if (isG1) {
            // gates1(t) from {h0(t), h1(t-1)}
            u64 a[5];
            #pragma unroll
            for (int k = 0; k < 5; ++k) a[k] = bp[k];
            #pragma unroll
            for (int m2 = 0; m2 < 10; ++m2) {
                float ha = h0[(2 * m2) * 16 + s16];
                float hb = h0[(2 * m2 + 1) * 16 + s16];
                u64 h2a = pk2(ha, ha), h2b = pk2(hb, hb);
                #pragma unroll
                for (int k = 0; k < 5; ++k) {
                    ulonglong2 wu = *reinterpret_cast<const ulonglong2*>(&w1s[(pb + k) * 40 + 2 * m2]);
                    a[k] = fma2(wu.x, h2a, a[k]);
                    a[k] = fma2(wu.y, h2b, a[k]);
                }
            }
            #pragma unroll
            for (int m2 = 0; m2 < 10; ++m2) {
                float ha = h1[(2 * m2) * 16 + s16];
                float hb = h1[(2 * m2 + 1) * 16 + s16];
                u64 h2a = pk2(ha, ha), h2b = pk2(hb, hb);
                #pragma unroll
                for (int k = 0; k < 5; ++k) {
                    ulonglong2 wv = *reinterpret_cast<const ulonglong2*>(&w1s[(pb + k) * 40 + 20 + 2 * m2]);
                    a[k] = fma2(wv.x, h2a, a[k]);
                    a[k] = fma2(wv.y, h2b, a[k]);
                }
            }
            #pragma unroll
            for (int k = 0; k < 5; ++k) g1[(pb + k) * 16 + s16] = a[k];
        } else {
            // gates0(t+1) from {x(t+1), h0(t)}
            float xv = (t + 1 < Tlen) ? xt_tile[((t + 1) & 15) * 16 + s16] : 0.f;
            u64 xv2 = pk2(xv, xv);
            u64 a[5];
            #pragma unroll
            for (int k = 0; k < 5; ++k) a[k] = fma2(wxp[k], xv2, bp[k]);
            #pragma unroll
            for (int m2 = 0; m2 < 10; ++m2) {
                float ha = h0[(2 * m2) * 16 + s16];
                float hb = h0[(2 * m2 + 1) * 16 + s16];
                u64 h2a = pk2(ha, ha), h2b = pk2(hb, hb);
                #pragma unroll
                for (int k = 0; k < 5; ++k) {
                    ulonglong2 w0 = *reinterpret_cast<const ulonglong2*>(&w0s[(pb + k) * 20 + 2 * m2]);
                    a[k] = fma2(w0.x, h2a, a[k]);
                    a[k] = fma2(w0.y, h2b, a[k]);
                }
            }
            #pragma unroll
            for (int k = 0; k < 5; ++k) g0[(pb + k) * 16 + s16] = a[k];
        }
        PBAR(P);
    }

    // ---- epilogue: cell1(T-1) -> h1(T-1), G1 warps ----
    if (isG1) {
        #pragma unroll
        for (int jj = 0; jj < 3; ++jj) {
            int uu = hwm + 8 * jj;
            if (uu < 20) {
                float gi, gf, ga, go;
                up2(gi, gf, g1[uu * 16 + s16]);
                up2(ga, go, g1[(20 + uu) * 16 + s16]);
                float ai = sigm_(gi), af = sigm_(gf);
                float ag = tanh_(ga), ao = sigm_(go);
                float cn = fmaf(af, cs[jj], ai * ag);
                cs[jj] = cn;
                h1[uu * 16 + s16] = ao * tanh_(cn);
            }
        }
    }
    PBAR(P);

    // ---- FC head: 16 threads per pipeline ----
    if (lt < 16) {
        float acc = __ldg(&fcb[0]);
        #pragma unroll
        for (int j = 0; j < 20; ++j)
            acc = fmaf(__ldg(&fcW[j]), h1[j * 16 + lt], acc);
        int bo = sbase + lt;
        if (bo < Btot) out[bo] = acc;
    }
}

extern "C" void kernel_launch(void* const* d_in, const int* in_sizes, int n_in,
                              void* d_out, int out_size)
{
    const float* x    = (const float*)d_in[0];
    const float* Wih0 = (const float*)d_in[1];
    const float* Whh0 = (const float*)d_in[2];
    const float* bih0 = (const float*)d_in[3];
    const float* bhh0 = (const float*)d_in[4];
    const float* Wih1 = (const float*)d_in[5];
    const float* Whh1 = (const float*)d_in[6];
    const float* bih1 = (const float*)d_in[7];
    const float* bhh1 = (const float*)d_in[8];
    const float* fcW  = (const float*)d_in[9];
    const float* fcb  = (const float*)d_in[10];

    const int B = out_size;              // out is [B, 1] fp32
    const int T = in_sizes[0] / B;       // x is [B, T, 1]
    const int blocks = (B + 31) / 32;    // 32 seqs per 512-thread block

    lstm2_fc_kernel<<<blocks, 512>>>(x, Wih0, Whh0, bih0, bhh0,
                                     Wih1, Whh1, bih1, bhh1,
                                     fcW, fcb, (float*)d_out, B, T);
}